// round 14
// baseline (speedup 1.0000x reference)
#include <cuda_runtime.h>
#include <cstdint>
#include <math.h>

#define NN 250000
#define EE 250000
#define D   128
#define HID 256
#define NT  256
#define BR  32
#define XS  34
#define HS  258

// ---- persistent device scratch ----
__device__ float g_Sp[(size_t)NN * D];    // zero-init; finalize_k re-zeroes each hop
__device__ float g_Sc[(size_t)NN * D];
__device__ float g_SpF[(size_t)NN * D];
__device__ float g_ScF[(size_t)NN * D];
__device__ int   g_cnt[2 * NN];
__device__ float g_inv[2 * NN];
__device__ float g_edge[2 * D];
__device__ float g_b1P[HID];
__device__ float g_b1C[HID];
// transposed weights [N][K]
__device__ float g_w1tV[256 * 128];
__device__ float g_w1tP[256 * 256];
__device__ float g_w1tC[256 * 256];
__device__ float g_w1tA[256 * 384];
__device__ float g_w2tV[128 * 256];
__device__ float g_w2tP[128 * 256];
__device__ float g_w2tC[128 * 256];
__device__ float g_w2tA[128 * 256];

__device__ __forceinline__ void ffma2(uint64_t& acc, uint64_t x, uint64_t w) {
    asm("fma.rn.f32x2 %0, %1, %2, %0;" : "+l"(acc) : "l"(x), "l"(w));
}
__device__ __forceinline__ float sum2(uint64_t v) {
    uint32_t lo, hi;
    asm("mov.b64 {%0,%1}, %2;" : "=r"(lo), "=r"(hi) : "l"(v));
    return __uint_as_float(lo) + __uint_as_float(hi);
}
__device__ __forceinline__ void redadd(float* p, float v) {
    asm volatile("red.global.add.f32 [%0], %1;" :: "l"(p), "f"(v) : "memory");
}
__device__ __forceinline__ uint32_t smem_u32(const void* p) {
    uint32_t a;
    asm("{ .reg .u64 t; cvta.to.shared.u64 t, %1; cvt.u32.u64 %0, t; }" : "=r"(a) : "l"(p));
    return a;
}
__device__ __forceinline__ void cp8(uint32_t s, const void* g) {
    asm volatile("cp.async.ca.shared.global [%0], [%1], 8;" :: "r"(s), "l"(g) : "memory");
}
#define CP_COMMIT() asm volatile("cp.async.commit_group;" ::: "memory")
#define CP_WAIT1()  asm volatile("cp.async.wait_group 1;" ::: "memory")

// ---------------- setup kernels (verbatim from passing R12) ----------------
__global__ void edge_const_k(const float* __restrict__ Ew1, const float* __restrict__ Eb1,
                             const float* __restrict__ Ew2, const float* __restrict__ Eb2) {
    __shared__ float hin[HID], hout[HID];
    int t = threadIdx.x;
    hin[t]  = fmaxf(Ew1[t] + Eb1[t], 0.f);
    hout[t] = fmaxf(Eb1[t], 0.f);
    __syncthreads();
    if (t < D) {
        float si = 0.f, so = 0.f;
        for (int j = 0; j < HID; j++) { float w = Ew2[j * D + t]; si += hin[j] * w; so += hout[j] * w; }
        g_edge[t]     = fmaxf(si + Eb2[t], 0.f);
        g_edge[D + t] = fmaxf(so + Eb2[t], 0.f);
    }
}
__global__ void fold_bias_k(const float* __restrict__ Pw1, const float* __restrict__ Pb1,
                            const float* __restrict__ Cw1, const float* __restrict__ Cb1) {
    int j = threadIdx.x;
    float sp = Pb1[j], sc = Cb1[j];
    for (int c = 0; c < D; c++) {
        sp += g_edge[D + c] * Pw1[(size_t)(2 * D + c) * HID + j];
        sc += g_edge[c]     * Cw1[(size_t)(2 * D + c) * HID + j];
    }
    g_b1P[j] = sp; g_b1C[j] = sc;
}
__global__ void zero_cnt_k() {
    int i = blockIdx.x * blockDim.x + threadIdx.x;
    if (i < 2 * NN) g_cnt[i] = 0;
}
__global__ void count_k(const int* __restrict__ si, const int* __restrict__ pi) {
    int e = blockIdx.x * blockDim.x + threadIdx.x;
    if (e < EE) { atomicAdd(&g_cnt[si[e]], 1); atomicAdd(&g_cnt[NN + pi[e]], 1); }
}
__global__ void inv_k() {
    int i = blockIdx.x * blockDim.x + threadIdx.x;
    if (i < 2 * NN) g_inv[i] = 1.f / fmaxf((float)g_cnt[i], 1.f);
}
__global__ void prep_w1_k(const float* __restrict__ W, int K, int id) {
    float* dst = id == 0 ? g_w1tV : id == 1 ? g_w1tP : id == 2 ? g_w1tC : g_w1tA;
    int i = blockIdx.x * blockDim.x + threadIdx.x;
    if (i < K * 256) { int k = i >> 8, n = i & 255; dst[(size_t)n * K + k] = W[i]; }
}
__global__ void prep_w2_k(const float* __restrict__ W, int id) {
    float* dst = id == 0 ? g_w2tV : id == 1 ? g_w2tP : id == 2 ? g_w2tC : g_w2tA;
    int i = blockIdx.x * blockDim.x + threadIdx.x;
    if (i < 256 * 128) { int k = i >> 7, n = i & 127; dst[(size_t)n * 256 + k] = W[i]; }
}
__global__ void finalize_k(const float* __restrict__ rmask, const float* __restrict__ lmask,
                           const float* __restrict__ stok, const float* __restrict__ etok) {
    int i = blockIdx.x * blockDim.x + threadIdx.x;
    if (i >= NN * 32) return;
    int row = i >> 5, q = i & 31;
    float ivp = g_inv[row], ivc = g_inv[NN + row];
    float rm = rmask[row], lm = lmask[row];
    float4 st = ((const float4*)stok)[q], et = ((const float4*)etok)[q];
    float4 z = make_float4(0.f, 0.f, 0.f, 0.f);
    float4 s = ((float4*)g_Sp)[i];
    float4 o;
    o.x = fmaf(s.x, ivp, rm * st.x); o.y = fmaf(s.y, ivp, rm * st.y);
    o.z = fmaf(s.z, ivp, rm * st.z); o.w = fmaf(s.w, ivp, rm * st.w);
    ((float4*)g_SpF)[i] = o; ((float4*)g_Sp)[i] = z;
    s = ((float4*)g_Sc)[i];
    o.x = fmaf(s.x, ivc, lm * et.x); o.y = fmaf(s.y, ivc, lm * et.y);
    o.z = fmaf(s.z, ivc, lm * et.z); o.w = fmaf(s.w, ivc, lm * et.w);
    ((float4*)g_ScF)[i] = o; ((float4*)g_Sc)[i] = z;
}

// ---------------------------------------------------------------------------
// Fused 2-layer MLP — cp.async pipeline (R12), BR=32 / acc[4][8] so that
// smem <= 78.6KB and 2 CTAs co-reside per SM (4 warps/SMSP).
// smem aliasing: phase A = X(2x4352)@0 + W1(2x34816)@8704;
//                phase B = Hs(33024)@0 + W2(2x17408)@43520.  All transitions
//                separated by the existing barriers.
// ---------------------------------------------------------------------------
#define OX    0
#define OW1   8704
#define OW2   43520
#define OH    0
#define OIDX  78336
#define SMEMSZ 78592

template <int KIN, int MODE, int TGT>
__global__ __launch_bounds__(NT, 2) void mlp7_k(
    int rows,
    const float* __restrict__ B1a, const float* __restrict__ B2,
    const float* __restrict__ srcA,
    const int* __restrict__ idxA, const int* __restrict__ idxB,
    float* __restrict__ dst)
{
    extern __shared__ char smc[];
    float* Hs = (float*)(smc + OH);
    int*   sA = (int*)(smc + OIDX);
    int*   sB = sA + BR;
    const uint32_t smb = smem_u32(smc);

    constexpr int NCH = KIN / 32;
    const float* W1T = MODE == 0 ? g_w1tV : MODE == 2 ? g_w1tA : (TGT == 0 ? g_w1tP : g_w1tC);
    const float* W2T = MODE == 0 ? g_w2tV : MODE == 2 ? g_w2tA : (TGT == 0 ? g_w2tP : g_w2tC);
    const float* B1  = (MODE == 1) ? (TGT == 0 ? (const float*)g_b1P : (const float*)g_b1C) : B1a;

    const int tid = threadIdx.x;
    const int wid = tid >> 5, lane = tid & 31;
    const int row0 = blockIdx.x * BR;

    if (MODE == 1 && tid < 2 * BR) {
        int r = tid & (BR - 1);
        int gr = row0 + r; if (gr >= rows) gr = rows - 1;
        if (tid < BR) sA[r] = idxA[gr]; else sB[r] = idxB[gr];
    }
    __syncthreads();

    auto stageA = [&](int c) {
        uint32_t xd = smb + OX + (c & 1) * 4352;
        uint32_t wd = smb + OW1 + (c & 1) * 34816;
        // X: 32 rows x 16 float2
#pragma unroll
        for (int i = 0; i < 2; i++) {
            int e = tid + i * NT;
            int r = e >> 4, s = e & 15;
            int gr = row0 + r; if (gr >= rows) gr = rows - 1;
            const float* src;
            if (MODE == 0) {
                src = srcA + (size_t)gr * D + c * 32 + s * 2;
            } else if (MODE == 1) {
                int idx = (c < 4 ? sA[r] : sB[r]);
                src = srcA + (size_t)idx * D + (c & 3) * 32 + s * 2;
            } else {
                const float* base = (c < 4) ? srcA : (c < 8) ? (const float*)g_SpF : (const float*)g_ScF;
                src = base + (size_t)gr * D + (c & 3) * 32 + s * 2;
            }
            cp8(xd + r * 136 + s * 8, src);
        }
        // W1: 256 n x 16 float2
#pragma unroll
        for (int i = 0; i < 16; i++) {
            int e = tid + i * NT;
            int n = e >> 4, s = e & 15;
            cp8(wd + n * 136 + s * 8, W1T + (size_t)n * KIN + c * 32 + s * 2);
        }
    };
    auto stageB = [&](int c) {
        uint32_t wd = smb + OW2 + (c & 1) * 17408;
#pragma unroll
        for (int i = 0; i < 8; i++) {
            int e = tid + i * NT;
            int n = e >> 4, s = e & 15;
            cp8(wd + n * 136 + s * 8, W2T + (size_t)n * 256 + c * 32 + s * 2);
        }
    };

    // ---------------- phase A: H = relu(X @ W1 + b1), N=256 ----------------
    uint64_t acc[4][8];
#pragma unroll
    for (int i = 0; i < 4; i++)
#pragma unroll
        for (int m = 0; m < 8; m++) acc[i][m] = 0ull;

    stageA(0); CP_COMMIT();
    for (int c = 0; c < NCH; c++) {
        if (c + 1 < NCH) stageA(c + 1);
        CP_COMMIT();
        CP_WAIT1();
        __syncthreads();
        const float* Xb = (const float*)(smc + OX + (c & 1) * 4352);
        const float* Wb = (const float*)(smc + OW1 + (c & 1) * 34816);
#pragma unroll
        for (int kp = 0; kp < 16; kp++) {
            uint64_t xp[4];
#pragma unroll
            for (int i = 0; i < 4; i++)
                xp[i] = *(const uint64_t*)&Xb[(wid * 4 + i) * XS + kp * 2];
#pragma unroll
            for (int m = 0; m < 8; m++) {
                uint64_t wv = *(const uint64_t*)&Wb[(m * 32 + lane) * XS + kp * 2];
#pragma unroll
                for (int i = 0; i < 4; i++) ffma2(acc[i][m], xp[i], wv);
            }
        }
        __syncthreads();
    }

    // prefetch first W2 chunk (into dead W1-buf region), overlap with epilogue A
    stageB(0); CP_COMMIT();

    // epilogue A -> Hs (aliases dead X/W1-buf0 region; barrier above guarantees safety)
#pragma unroll
    for (int m = 0; m < 8; m++) {
        int col = m * 32 + lane;
        float b = B1[col];
#pragma unroll
        for (int i = 0; i < 4; i++)
            Hs[(wid * 4 + i) * HS + col] = fmaxf(sum2(acc[i][m]) + b, 0.f);
    }

    // ---------------- phase B: Y = relu(H @ W2 + b2), N=128 ----------------
    uint64_t acc2[4][4];
#pragma unroll
    for (int i = 0; i < 4; i++)
#pragma unroll
        for (int m = 0; m < 4; m++) acc2[i][m] = 0ull;

    for (int c = 0; c < 8; c++) {
        if (c + 1 < 8) stageB(c + 1);
        CP_COMMIT();
        CP_WAIT1();
        __syncthreads();
        const float* Wb = (const float*)(smc + OW2 + (c & 1) * 17408);
#pragma unroll
        for (int kp = 0; kp < 16; kp++) {
            uint64_t xp[4];
#pragma unroll
            for (int i = 0; i < 4; i++)
                xp[i] = *(const uint64_t*)&Hs[(wid * 4 + i) * HS + c * 32 + kp * 2];
#pragma unroll
            for (int m = 0; m < 4; m++) {
                uint64_t wv = *(const uint64_t*)&Wb[(m * 32 + lane) * XS + kp * 2];
#pragma unroll
                for (int i = 0; i < 4; i++) ffma2(acc2[i][m], xp[i], wv);
            }
        }
        __syncthreads();
    }

    // ---------------- epilogue B ----------------
#pragma unroll
    for (int i = 0; i < 4; i++) {
        int r = wid * 4 + i;
        int gr = row0 + r;
        if (gr >= rows) continue;
#pragma unroll
        for (int m = 0; m < 4; m++) {
            int col = m * 32 + lane;
            float y = fmaxf(sum2(acc2[i][m]) + B2[col], 0.f);
            if (MODE == 1) {
                redadd((TGT == 0 ? g_Sp : g_Sc) + (size_t)sB[r] * D + col, y);
            } else if (MODE == 0) {
                dst[(size_t)gr * D + col] = y;
            } else {
                size_t o = (size_t)gr * D + col;
                dst[o] = dst[o] + y;
            }
        }
    }
}

// ---------------------------------------------------------------------------
extern "C" void kernel_launch(void* const* d_in, const int* in_sizes, int n_in,
                              void* d_out, int out_size) {
    const float* bt    = (const float*)d_in[0];
    const int*   si    = (const int*)  d_in[1];
    const int*   pi    = (const int*)  d_in[2];
    const float* rmask = (const float*)d_in[3];
    const float* lmask = (const float*)d_in[4];
    const float* stok  = (const float*)d_in[5];
    const float* etok  = (const float*)d_in[6];
    const float* Vw1 = (const float*)d_in[7],  *Vb1 = (const float*)d_in[8];
    const float* Vw2 = (const float*)d_in[9],  *Vb2 = (const float*)d_in[10];
    const float* Ew1 = (const float*)d_in[11], *Eb1 = (const float*)d_in[12];
    const float* Ew2 = (const float*)d_in[13], *Eb2 = (const float*)d_in[14];
    const float* Pw1 = (const float*)d_in[15], *Pb1 = (const float*)d_in[16];
    const float* Pw2 = (const float*)d_in[17], *Pb2 = (const float*)d_in[18];
    const float* Cw1 = (const float*)d_in[19], *Cb1 = (const float*)d_in[20];
    const float* Cw2 = (const float*)d_in[21], *Cb2 = (const float*)d_in[22];
    const float* Aw1 = (const float*)d_in[23], *Ab1 = (const float*)d_in[24];
    const float* Aw2 = (const float*)d_in[25], *Ab2 = (const float*)d_in[26];
    float* hid = (float*)d_out;

    cudaFuncSetAttribute(mlp7_k<128, 0, 0>, cudaFuncAttributeMaxDynamicSharedMemorySize, SMEMSZ);
    cudaFuncSetAttribute(mlp7_k<256, 1, 0>, cudaFuncAttributeMaxDynamicSharedMemorySize, SMEMSZ);
    cudaFuncSetAttribute(mlp7_k<256, 1, 1>, cudaFuncAttributeMaxDynamicSharedMemorySize, SMEMSZ);
    cudaFuncSetAttribute(mlp7_k<384, 2, 0>, cudaFuncAttributeMaxDynamicSharedMemorySize, SMEMSZ);

    edge_const_k<<<1, 256>>>(Ew1, Eb1, Ew2, Eb2);
    fold_bias_k<<<1, 256>>>(Pw1, Pb1, Cw1, Cb1);
    zero_cnt_k<<<(2 * NN + 255) / 256, 256>>>();
    count_k<<<(EE + 255) / 256, 256>>>(si, pi);
    inv_k<<<(2 * NN + 255) / 256, 256>>>();
    prep_w1_k<<<128, 256>>>(Vw1, 128, 0);
    prep_w1_k<<<256, 256>>>(Pw1, 256, 1);
    prep_w1_k<<<256, 256>>>(Cw1, 256, 2);
    prep_w1_k<<<384, 256>>>(Aw1, 384, 3);
    prep_w2_k<<<128, 256>>>(Vw2, 0);
    prep_w2_k<<<128, 256>>>(Pw2, 1);
    prep_w2_k<<<128, 256>>>(Cw2, 2);
    prep_w2_k<<<128, 256>>>(Aw2, 3);

    const int gb = (NN + BR - 1) / BR;
    mlp7_k<128, 0, 0><<<gb, NT, SMEMSZ>>>(NN, Vb1, Vb2, bt, nullptr, nullptr, hid);
    for (int h = 0; h < 3; h++) {
        mlp7_k<256, 1, 0><<<gb, NT, SMEMSZ>>>(EE, nullptr, Pb2, hid, pi, si, nullptr);
        mlp7_k<256, 1, 1><<<gb, NT, SMEMSZ>>>(EE, nullptr, Cb2, hid, si, pi, nullptr);
        finalize_k<<<(NN * 32 + 255) / 256, 256>>>(rmask, lmask, stok, etok);
        mlp7_k<384, 2, 0><<<gb, NT, SMEMSZ>>>(NN, Ab1, Ab2, hid, nullptr, nullptr, hid);
    }
}

// round 15
// speedup vs baseline: 1.0662x; 1.0662x over previous
#include <cuda_runtime.h>
#include <cstdint>
#include <math.h>

#define NN 250000
#define EE 250000
#define D   128
#define HID 256
#define NT  256
#define BR  64
#define XS  34
#define HS  258

// ---- persistent device scratch ----
__device__ float g_Sp[(size_t)NN * D];    // zero-init; finalize_k re-zeroes each hop
__device__ float g_Sc[(size_t)NN * D];
__device__ float g_SpF[(size_t)NN * D];
__device__ float g_ScF[(size_t)NN * D];
__device__ int   g_cnt[2 * NN];
__device__ float g_inv[2 * NN];
__device__ float g_edge[2 * D];
__device__ float g_b1P[HID];
__device__ float g_b1C[HID];
// transposed weights [N][K]
__device__ float g_w1tV[256 * 128];
__device__ float g_w1tP[256 * 256];
__device__ float g_w1tC[256 * 256];
__device__ float g_w1tA[256 * 384];
__device__ float g_w2tV[128 * 256];
__device__ float g_w2tP[128 * 256];
__device__ float g_w2tC[128 * 256];
__device__ float g_w2tA[128 * 256];

__device__ __forceinline__ void ffma2(uint64_t& acc, uint64_t x, uint64_t w) {
    asm("fma.rn.f32x2 %0, %1, %2, %0;" : "+l"(acc) : "l"(x), "l"(w));
}
__device__ __forceinline__ float sum2(uint64_t v) {
    uint32_t lo, hi;
    asm("mov.b64 {%0,%1}, %2;" : "=r"(lo), "=r"(hi) : "l"(v));
    return __uint_as_float(lo) + __uint_as_float(hi);
}
__device__ __forceinline__ void redadd(float* p, float v) {
    asm volatile("red.global.add.f32 [%0], %1;" :: "l"(p), "f"(v) : "memory");
}
__device__ __forceinline__ uint32_t smem_u32(const void* p) {
    uint32_t a;
    asm("{ .reg .u64 t; cvta.to.shared.u64 t, %1; cvt.u32.u64 %0, t; }" : "=r"(a) : "l"(p));
    return a;
}
__device__ __forceinline__ void cp8(uint32_t s, const void* g) {
    asm volatile("cp.async.ca.shared.global [%0], [%1], 8;" :: "r"(s), "l"(g) : "memory");
}
#define CP_COMMIT() asm volatile("cp.async.commit_group;" ::: "memory")
#define CP_WAIT1()  asm volatile("cp.async.wait_group 1;" ::: "memory")

// ---------------- setup kernels ----------------
__global__ void edge_const_k(const float* __restrict__ Ew1, const float* __restrict__ Eb1,
                             const float* __restrict__ Ew2, const float* __restrict__ Eb2) {
    __shared__ float hin[HID], hout[HID];
    int t = threadIdx.x;
    hin[t]  = fmaxf(Ew1[t] + Eb1[t], 0.f);
    hout[t] = fmaxf(Eb1[t], 0.f);
    __syncthreads();
    if (t < D) {
        float si = 0.f, so = 0.f;
        for (int j = 0; j < HID; j++) { float w = Ew2[j * D + t]; si += hin[j] * w; so += hout[j] * w; }
        g_edge[t]     = fmaxf(si + Eb2[t], 0.f);
        g_edge[D + t] = fmaxf(so + Eb2[t], 0.f);
    }
}
__global__ void fold_bias_k(const float* __restrict__ Pw1, const float* __restrict__ Pb1,
                            const float* __restrict__ Cw1, const float* __restrict__ Cb1) {
    int j = threadIdx.x;
    float sp = Pb1[j], sc = Cb1[j];
    for (int c = 0; c < D; c++) {
        sp += g_edge[D + c] * Pw1[(size_t)(2 * D + c) * HID + j];
        sc += g_edge[c]     * Cw1[(size_t)(2 * D + c) * HID + j];
    }
    g_b1P[j] = sp; g_b1C[j] = sc;
}
__global__ void zero_cnt_k() {
    int i = blockIdx.x * blockDim.x + threadIdx.x;
    if (i < 2 * NN) g_cnt[i] = 0;
}
__global__ void count_k(const int* __restrict__ si, const int* __restrict__ pi) {
    int e = blockIdx.x * blockDim.x + threadIdx.x;
    if (e < EE) { atomicAdd(&g_cnt[si[e]], 1); atomicAdd(&g_cnt[NN + pi[e]], 1); }
}
__global__ void inv_k() {
    int i = blockIdx.x * blockDim.x + threadIdx.x;
    if (i < 2 * NN) g_inv[i] = 1.f / fmaxf((float)g_cnt[i], 1.f);
}
__global__ void prep_w1_k(const float* __restrict__ W, int K, int id) {
    float* dst = id == 0 ? g_w1tV : id == 1 ? g_w1tP : id == 2 ? g_w1tC : g_w1tA;
    int i = blockIdx.x * blockDim.x + threadIdx.x;
    if (i < K * 256) { int k = i >> 8, n = i & 255; dst[(size_t)n * K + k] = W[i]; }
}
__global__ void prep_w2_k(const float* __restrict__ W, int id) {
    float* dst = id == 0 ? g_w2tV : id == 1 ? g_w2tP : id == 2 ? g_w2tC : g_w2tA;
    int i = blockIdx.x * blockDim.x + threadIdx.x;
    if (i < 256 * 128) { int k = i >> 7, n = i & 127; dst[(size_t)n * 256 + k] = W[i]; }
}
__global__ void finalize_k(const float* __restrict__ rmask, const float* __restrict__ lmask,
                           const float* __restrict__ stok, const float* __restrict__ etok) {
    int i = blockIdx.x * blockDim.x + threadIdx.x;
    if (i >= NN * 32) return;
    int row = i >> 5, q = i & 31;
    float ivp = g_inv[row], ivc = g_inv[NN + row];
    float rm = rmask[row], lm = lmask[row];
    float4 st = ((const float4*)stok)[q], et = ((const float4*)etok)[q];
    float4 z = make_float4(0.f, 0.f, 0.f, 0.f);
    float4 s = ((float4*)g_Sp)[i];
    float4 o;
    o.x = fmaf(s.x, ivp, rm * st.x); o.y = fmaf(s.y, ivp, rm * st.y);
    o.z = fmaf(s.z, ivp, rm * st.z); o.w = fmaf(s.w, ivp, rm * st.w);
    ((float4*)g_SpF)[i] = o; ((float4*)g_Sp)[i] = z;
    s = ((float4*)g_Sc)[i];
    o.x = fmaf(s.x, ivc, lm * et.x); o.y = fmaf(s.y, ivc, lm * et.y);
    o.z = fmaf(s.z, ivc, lm * et.z); o.w = fmaf(s.w, ivc, lm * et.w);
    ((float4*)g_ScF)[i] = o; ((float4*)g_Sc)[i] = z;
}

// ---------------------------------------------------------------------------
// Fused 2-layer MLP — R12 compute micro-kernel (BR=64, 256 thr, 8 rows/warp),
// 3-stage cp.async pipeline, ONE __syncthreads per K-chunk.
//   iter c: WAIT1 -> sync -> stage(c+2) -> commit -> compute(c)
// Buffer residues c, c+1, c+2 are distinct mod 3 -> no cross-warp clobber.
// smem: phase A: X 3x8704 @0, W1 3x34816 @26112 (end 130560)
//       phase B: Hs 66048 @0 (aliases X+W1buf0/1, after full sync),
//                W2 3x17408 @66048 (aliases W1buf1/2, after full sync)
// ---------------------------------------------------------------------------
#define OX    0
#define OW1   26112
#define OH    0
#define OW2   66048
#define OIDX  130560
#define SMEMSZ 131072

template <int KIN, int MODE, int TGT>
__global__ __launch_bounds__(NT, 1) void mlp8_k(
    int rows,
    const float* __restrict__ B1a, const float* __restrict__ B2,
    const float* __restrict__ srcA,
    const int* __restrict__ idxA, const int* __restrict__ idxB,
    float* __restrict__ dst)
{
    extern __shared__ char smc[];
    float* Hs = (float*)(smc + OH);
    int*   sA = (int*)(smc + OIDX);
    int*   sB = sA + BR;
    const uint32_t smb = smem_u32(smc);

    constexpr int NCH = KIN / 32;
    const float* W1T = MODE == 0 ? g_w1tV : MODE == 2 ? g_w1tA : (TGT == 0 ? g_w1tP : g_w1tC);
    const float* W2T = MODE == 0 ? g_w2tV : MODE == 2 ? g_w2tA : (TGT == 0 ? g_w2tP : g_w2tC);
    const float* B1  = (MODE == 1) ? (TGT == 0 ? (const float*)g_b1P : (const float*)g_b1C) : B1a;

    const int tid = threadIdx.x;
    const int wid = tid >> 5, lane = tid & 31;
    const int row0 = blockIdx.x * BR;

    if (MODE == 1 && tid < 2 * BR) {
        int r = tid & (BR - 1);
        int gr = row0 + r; if (gr >= rows) gr = rows - 1;
        if (tid < BR) sA[r] = idxA[gr]; else sB[r] = idxB[gr];
    }
    __syncthreads();

    auto stageA = [&](int c) {
        uint32_t xd = smb + OX + (c % 3) * 8704;
        uint32_t wd = smb + OW1 + (c % 3) * 34816;
        // X: 64 rows x 16 float2
#pragma unroll
        for (int i = 0; i < 4; i++) {
            int e = tid + i * NT;
            int r = e >> 4, s = e & 15;
            int gr = row0 + r; if (gr >= rows) gr = rows - 1;
            const float* src;
            if (MODE == 0) {
                src = srcA + (size_t)gr * D + c * 32 + s * 2;
            } else if (MODE == 1) {
                int idx = (c < 4 ? sA[r] : sB[r]);
                src = srcA + (size_t)idx * D + (c & 3) * 32 + s * 2;
            } else {
                const float* base = (c < 4) ? srcA : (c < 8) ? (const float*)g_SpF : (const float*)g_ScF;
                src = base + (size_t)gr * D + (c & 3) * 32 + s * 2;
            }
            cp8(xd + r * 136 + s * 8, src);
        }
        // W1: 256 n x 16 float2
#pragma unroll
        for (int i = 0; i < 16; i++) {
            int e = tid + i * NT;
            int n = e >> 4, s = e & 15;
            cp8(wd + n * 136 + s * 8, W1T + (size_t)n * KIN + c * 32 + s * 2);
        }
    };
    auto stageB = [&](int c) {
        uint32_t wd = smb + OW2 + (c % 3) * 17408;
#pragma unroll
        for (int i = 0; i < 8; i++) {
            int e = tid + i * NT;
            int n = e >> 4, s = e & 15;
            cp8(wd + n * 136 + s * 8, W2T + (size_t)n * 256 + c * 32 + s * 2);
        }
    };

    // ---------------- phase A: H = relu(X @ W1 + b1), N=256 ----------------
    uint64_t acc[8][8];
#pragma unroll
    for (int i = 0; i < 8; i++)
#pragma unroll
        for (int m = 0; m < 8; m++) acc[i][m] = 0ull;

    stageA(0); CP_COMMIT();
    stageA(1); CP_COMMIT();
    for (int c = 0; c < NCH; c++) {
        CP_WAIT1();              // chunk c complete (one commit per iter below)
        __syncthreads();         // all warps past compute(c-1); data visible
        if (c + 2 < NCH) stageA(c + 2);
        CP_COMMIT();             // exactly one group per iteration (may be empty)
        const float* Xb = (const float*)(smc + OX + (c % 3) * 8704);
        const float* Wb = (const float*)(smc + OW1 + (c % 3) * 34816);
#pragma unroll
        for (int kp = 0; kp < 16; kp++) {
            uint64_t xp[8];
#pragma unroll
            for (int i = 0; i < 8; i++)
                xp[i] = *(const uint64_t*)&Xb[(wid * 8 + i) * XS + kp * 2];
#pragma unroll
            for (int m = 0; m < 8; m++) {
                uint64_t wv = *(const uint64_t*)&Wb[(m * 32 + lane) * XS + kp * 2];
#pragma unroll
                for (int i = 0; i < 8; i++) ffma2(acc[i][m], xp[i], wv);
            }
        }
    }

    __syncthreads();             // all warps done with W1/X bufs (Hs/W2 alias them)
    stageB(0); CP_COMMIT();
    stageB(1); CP_COMMIT();

    // epilogue A -> Hs (same-warp rows only; overlaps W2 prefetch)
#pragma unroll
    for (int m = 0; m < 8; m++) {
        int col = m * 32 + lane;
        float b = B1[col];
#pragma unroll
        for (int i = 0; i < 8; i++)
            Hs[(wid * 8 + i) * HS + col] = fmaxf(sum2(acc[i][m]) + b, 0.f);
    }

    // ---------------- phase B: Y = relu(H @ W2 + b2), N=128 ----------------
    uint64_t acc2[8][4];
#pragma unroll
    for (int i = 0; i < 8; i++)
#pragma unroll
        for (int m = 0; m < 4; m++) acc2[i][m] = 0ull;

    for (int c = 0; c < 8; c++) {
        CP_WAIT1();
        __syncthreads();
        if (c + 2 < 8) stageB(c + 2);
        CP_COMMIT();
        const float* Wb = (const float*)(smc + OW2 + (c % 3) * 17408);
#pragma unroll
        for (int kp = 0; kp < 16; kp++) {
            uint64_t xp[8];
#pragma unroll
            for (int i = 0; i < 8; i++)
                xp[i] = *(const uint64_t*)&Hs[(wid * 8 + i) * HS + c * 32 + kp * 2];
#pragma unroll
            for (int m = 0; m < 4; m++) {
                uint64_t wv = *(const uint64_t*)&Wb[(m * 32 + lane) * XS + kp * 2];
#pragma unroll
                for (int i = 0; i < 8; i++) ffma2(acc2[i][m], xp[i], wv);
            }
        }
    }

    // ---------------- epilogue B ----------------
#pragma unroll
    for (int i = 0; i < 8; i++) {
        int r = wid * 8 + i;
        int gr = row0 + r;
        if (gr >= rows) continue;
#pragma unroll
        for (int m = 0; m < 4; m++) {
            int col = m * 32 + lane;
            float y = fmaxf(sum2(acc2[i][m]) + B2[col], 0.f);
            if (MODE == 1) {
                redadd((TGT == 0 ? g_Sp : g_Sc) + (size_t)sB[r] * D + col, y);
            } else if (MODE == 0) {
                dst[(size_t)gr * D + col] = y;
            } else {
                size_t o = (size_t)gr * D + col;
                dst[o] = dst[o] + y;
            }
        }
    }
}

// ---------------------------------------------------------------------------
extern "C" void kernel_launch(void* const* d_in, const int* in_sizes, int n_in,
                              void* d_out, int out_size) {
    const float* bt    = (const float*)d_in[0];
    const int*   si    = (const int*)  d_in[1];
    const int*   pi    = (const int*)  d_in[2];
    const float* rmask = (const float*)d_in[3];
    const float* lmask = (const float*)d_in[4];
    const float* stok  = (const float*)d_in[5];
    const float* etok  = (const float*)d_in[6];
    const float* Vw1 = (const float*)d_in[7],  *Vb1 = (const float*)d_in[8];
    const float* Vw2 = (const float*)d_in[9],  *Vb2 = (const float*)d_in[10];
    const float* Ew1 = (const float*)d_in[11], *Eb1 = (const float*)d_in[12];
    const float* Ew2 = (const float*)d_in[13], *Eb2 = (const float*)d_in[14];
    const float* Pw1 = (const float*)d_in[15], *Pb1 = (const float*)d_in[16];
    const float* Pw2 = (const float*)d_in[17], *Pb2 = (const float*)d_in[18];
    const float* Cw1 = (const float*)d_in[19], *Cb1 = (const float*)d_in[20];
    const float* Cw2 = (const float*)d_in[21], *Cb2 = (const float*)d_in[22];
    const float* Aw1 = (const float*)d_in[23], *Ab1 = (const float*)d_in[24];
    const float* Aw2 = (const float*)d_in[25], *Ab2 = (const float*)d_in[26];
    float* hid = (float*)d_out;

    cudaFuncSetAttribute(mlp8_k<128, 0, 0>, cudaFuncAttributeMaxDynamicSharedMemorySize, SMEMSZ);
    cudaFuncSetAttribute(mlp8_k<256, 1, 0>, cudaFuncAttributeMaxDynamicSharedMemorySize, SMEMSZ);
    cudaFuncSetAttribute(mlp8_k<256, 1, 1>, cudaFuncAttributeMaxDynamicSharedMemorySize, SMEMSZ);
    cudaFuncSetAttribute(mlp8_k<384, 2, 0>, cudaFuncAttributeMaxDynamicSharedMemorySize, SMEMSZ);

    // launches 1-5, then the V MLP as launch #6 so ncu (-s 5 -c 1) profiles it
    zero_cnt_k<<<(2 * NN + 255) / 256, 256>>>();
    count_k<<<(EE + 255) / 256, 256>>>(si, pi);
    inv_k<<<(2 * NN + 255) / 256, 256>>>();
    prep_w1_k<<<128, 256>>>(Vw1, 128, 0);
    prep_w2_k<<<128, 256>>>(Vw2, 0);

    const int gb = (NN + BR - 1) / BR;
    mlp8_k<128, 0, 0><<<gb, NT, SMEMSZ>>>(NN, Vb1, Vb2, bt, nullptr, nullptr, hid);

    edge_const_k<<<1, 256>>>(Ew1, Eb1, Ew2, Eb2);
    fold_bias_k<<<1, 256>>>(Pw1, Pb1, Cw1, Cb1);
    prep_w1_k<<<256, 256>>>(Pw1, 256, 1);
    prep_w1_k<<<256, 256>>>(Cw1, 256, 2);
    prep_w1_k<<<384, 256>>>(Aw1, 384, 3);
    prep_w2_k<<<128, 256>>>(Pw2, 1);
    prep_w2_k<<<128, 256>>>(Cw2, 2);
    prep_w2_k<<<128, 256>>>(Aw2, 3);

    for (int h = 0; h < 3; h++) {
        mlp8_k<256, 1, 0><<<gb, NT, SMEMSZ>>>(EE, nullptr, Pb2, hid, pi, si, nullptr);
        mlp8_k<256, 1, 1><<<gb, NT, SMEMSZ>>>(EE, nullptr, Cb2, hid, si, pi, nullptr);
        finalize_k<<<(NN * 32 + 255) / 256, 256>>>(rmask, lmask, stok, etok);
        mlp8_k<384, 2, 0><<<gb, NT, SMEMSZ>>>(NN, Ab1, Ab2, hid, nullptr, nullptr, hid);
    }
}

// round 16
// speedup vs baseline: 1.0819x; 1.0147x over previous
#include <cuda_runtime.h>
#include <cstdint>
#include <math.h>

#define NN 250000
#define EE 250000
#define D   128
#define HID 256
#define NT  256
#define BR  64
#define XS  34
#define HS  258

// ---- persistent device scratch ----
__device__ float g_Sp[(size_t)NN * D];    // zero-init; finalize_k re-zeroes each hop
__device__ float g_Sc[(size_t)NN * D];
__device__ float g_SpF[(size_t)NN * D];
__device__ float g_ScF[(size_t)NN * D];
__device__ int   g_cnt[2 * NN];
__device__ float g_inv[2 * NN];
__device__ float g_edge[2 * D];
__device__ float g_b1P[HID];
__device__ float g_b1C[HID];
// transposed weights [N][K]
__device__ float g_w1tV[256 * 128];
__device__ float g_w1tP[256 * 256];
__device__ float g_w1tC[256 * 256];
__device__ float g_w1tA[256 * 384];
__device__ float g_w2tV[128 * 256];
__device__ float g_w2tP[128 * 256];
__device__ float g_w2tC[128 * 256];
__device__ float g_w2tA[128 * 256];

__device__ __forceinline__ void ffma2(uint64_t& acc, uint64_t x, uint64_t w) {
    asm("fma.rn.f32x2 %0, %1, %2, %0;" : "+l"(acc) : "l"(x), "l"(w));
}
__device__ __forceinline__ float sum2(uint64_t v) {
    uint32_t lo, hi;
    asm("mov.b64 {%0,%1}, %2;" : "=r"(lo), "=r"(hi) : "l"(v));
    return __uint_as_float(lo) + __uint_as_float(hi);
}
__device__ __forceinline__ void red4(float* p, float4 v) {
    asm volatile("red.global.add.v4.f32 [%0], {%1,%2,%3,%4};"
                 :: "l"(p), "f"(v.x), "f"(v.y), "f"(v.z), "f"(v.w) : "memory");
}
__device__ __forceinline__ uint32_t smem_u32(const void* p) {
    uint32_t a;
    asm("{ .reg .u64 t; cvta.to.shared.u64 t, %1; cvt.u32.u64 %0, t; }" : "=r"(a) : "l"(p));
    return a;
}
__device__ __forceinline__ void cp8(uint32_t s, const void* g) {
    asm volatile("cp.async.ca.shared.global [%0], [%1], 8;" :: "r"(s), "l"(g) : "memory");
}
#define CP_COMMIT() asm volatile("cp.async.commit_group;" ::: "memory")
#define CP_WAIT1()  asm volatile("cp.async.wait_group 1;" ::: "memory")

// ---------------- setup kernels ----------------
__global__ void edge_const_k(const float* __restrict__ Ew1, const float* __restrict__ Eb1,
                             const float* __restrict__ Ew2, const float* __restrict__ Eb2) {
    __shared__ float hin[HID], hout[HID];
    int t = threadIdx.x;
    hin[t]  = fmaxf(Ew1[t] + Eb1[t], 0.f);
    hout[t] = fmaxf(Eb1[t], 0.f);
    __syncthreads();
    if (t < D) {
        float si = 0.f, so = 0.f;
        for (int j = 0; j < HID; j++) { float w = Ew2[j * D + t]; si += hin[j] * w; so += hout[j] * w; }
        g_edge[t]     = fmaxf(si + Eb2[t], 0.f);
        g_edge[D + t] = fmaxf(so + Eb2[t], 0.f);
    }
}
__global__ void fold_bias_k(const float* __restrict__ Pw1, const float* __restrict__ Pb1,
                            const float* __restrict__ Cw1, const float* __restrict__ Cb1) {
    int j = threadIdx.x;
    float sp = Pb1[j], sc = Cb1[j];
    for (int c = 0; c < D; c++) {
        sp += g_edge[D + c] * Pw1[(size_t)(2 * D + c) * HID + j];
        sc += g_edge[c]     * Cw1[(size_t)(2 * D + c) * HID + j];
    }
    g_b1P[j] = sp; g_b1C[j] = sc;
}
__global__ void zero_cnt_k() {
    int i = blockIdx.x * blockDim.x + threadIdx.x;
    if (i < 2 * NN) g_cnt[i] = 0;
}
__global__ void count_k(const int* __restrict__ si, const int* __restrict__ pi) {
    int e = blockIdx.x * blockDim.x + threadIdx.x;
    if (e < EE) { atomicAdd(&g_cnt[si[e]], 1); atomicAdd(&g_cnt[NN + pi[e]], 1); }
}
__global__ void inv_k() {
    int i = blockIdx.x * blockDim.x + threadIdx.x;
    if (i < 2 * NN) g_inv[i] = 1.f / fmaxf((float)g_cnt[i], 1.f);
}
__global__ void prep_w1_k(const float* __restrict__ W, int K, int id) {
    float* dst = id == 0 ? g_w1tV : id == 1 ? g_w1tP : id == 2 ? g_w1tC : g_w1tA;
    int i = blockIdx.x * blockDim.x + threadIdx.x;
    if (i < K * 256) { int k = i >> 8, n = i & 255; dst[(size_t)n * K + k] = W[i]; }
}
__global__ void prep_w2_k(const float* __restrict__ W, int id) {
    float* dst = id == 0 ? g_w2tV : id == 1 ? g_w2tP : id == 2 ? g_w2tC : g_w2tA;
    int i = blockIdx.x * blockDim.x + threadIdx.x;
    if (i < 256 * 128) { int k = i >> 7, n = i & 127; dst[(size_t)n * 256 + k] = W[i]; }
}
__global__ void finalize_k(const float* __restrict__ rmask, const float* __restrict__ lmask,
                           const float* __restrict__ stok, const float* __restrict__ etok) {
    int i = blockIdx.x * blockDim.x + threadIdx.x;
    if (i >= NN * 32) return;
    int row = i >> 5, q = i & 31;
    float ivp = g_inv[row], ivc = g_inv[NN + row];
    float rm = rmask[row], lm = lmask[row];
    float4 st = ((const float4*)stok)[q], et = ((const float4*)etok)[q];
    float4 z = make_float4(0.f, 0.f, 0.f, 0.f);
    float4 s = ((float4*)g_Sp)[i];
    float4 o;
    o.x = fmaf(s.x, ivp, rm * st.x); o.y = fmaf(s.y, ivp, rm * st.y);
    o.z = fmaf(s.z, ivp, rm * st.z); o.w = fmaf(s.w, ivp, rm * st.w);
    ((float4*)g_SpF)[i] = o; ((float4*)g_Sp)[i] = z;
    s = ((float4*)g_Sc)[i];
    o.x = fmaf(s.x, ivc, lm * et.x); o.y = fmaf(s.y, ivc, lm * et.y);
    o.z = fmaf(s.z, ivc, lm * et.z); o.w = fmaf(s.w, ivc, lm * et.w);
    ((float4*)g_ScF)[i] = o; ((float4*)g_Sc)[i] = z;
}

// ---------------------------------------------------------------------------
// Fused 2-layer MLP — R12 pipeline verbatim (BR=64, 256 thr, 8 rows/warp,
// double-buffered cp.async, stage-before-wait). ONLY change: epilogue B
// round-trips y through smem so global writes are contiguous float4
// (red.global.add.v4 / STG.128) instead of 32 strided scalars.
// ---------------------------------------------------------------------------
#define OFF_X   0          // 2 x 8704
#define OFF_W   17408      // 2 x 34816
#define OFF_H   87040      // 66048 (Hs; reused as Ys stride-132 in epilogue B)
#define OFF_IDX 153088     // 128 ints
#define SMEMSZ  153600

template <int KIN, int MODE, int TGT>
__global__ __launch_bounds__(NT, 1) void mlp9_k(
    int rows,
    const float* __restrict__ B1a, const float* __restrict__ B2,
    const float* __restrict__ srcA,
    const int* __restrict__ idxA, const int* __restrict__ idxB,
    float* __restrict__ dst)
{
    extern __shared__ char smc[];
    float* Hs = (float*)(smc + OFF_H);
    int*   sA = (int*)(smc + OFF_IDX);
    int*   sB = sA + BR;
    const uint32_t smb = smem_u32(smc);

    constexpr int NCH = KIN / 32;
    const float* W1T = MODE == 0 ? g_w1tV : MODE == 2 ? g_w1tA : (TGT == 0 ? g_w1tP : g_w1tC);
    const float* W2T = MODE == 0 ? g_w2tV : MODE == 2 ? g_w2tA : (TGT == 0 ? g_w2tP : g_w2tC);
    const float* B1  = (MODE == 1) ? (TGT == 0 ? (const float*)g_b1P : (const float*)g_b1C) : B1a;

    const int tid = threadIdx.x;
    const int wid = tid >> 5, lane = tid & 31;
    const int row0 = blockIdx.x * BR;

    if (MODE == 1 && tid < 2 * BR) {
        int r = tid & (BR - 1);
        int gr = row0 + r; if (gr >= rows) gr = rows - 1;
        if (tid < BR) sA[r] = idxA[gr]; else sB[r] = idxB[gr];
    }
    __syncthreads();

    auto stageA = [&](int c) {
        uint32_t xd = smb + OFF_X + (c & 1) * 8704;
        uint32_t wd = smb + OFF_W + (c & 1) * 34816;
#pragma unroll
        for (int i = 0; i < 4; i++) {
            int e = tid + i * NT;
            int r = e >> 4, s = e & 15;
            int gr = row0 + r; if (gr >= rows) gr = rows - 1;
            const float* src;
            if (MODE == 0) {
                src = srcA + (size_t)gr * D + c * 32 + s * 2;
            } else if (MODE == 1) {
                int idx = (c < 4 ? sA[r] : sB[r]);
                src = srcA + (size_t)idx * D + (c & 3) * 32 + s * 2;
            } else {
                const float* base = (c < 4) ? srcA : (c < 8) ? (const float*)g_SpF : (const float*)g_ScF;
                src = base + (size_t)gr * D + (c & 3) * 32 + s * 2;
            }
            cp8(xd + r * 136 + s * 8, src);
        }
#pragma unroll
        for (int i = 0; i < 16; i++) {
            int e = tid + i * NT;
            int n = e >> 4, s = e & 15;
            cp8(wd + n * 136 + s * 8, W1T + (size_t)n * KIN + c * 32 + s * 2);
        }
    };
    auto stageB = [&](int c) {
        uint32_t wd = smb + OFF_W + (c & 1) * 34816;
#pragma unroll
        for (int i = 0; i < 8; i++) {
            int e = tid + i * NT;
            int n = e >> 4, s = e & 15;
            cp8(wd + n * 136 + s * 8, W2T + (size_t)n * 256 + c * 32 + s * 2);
        }
    };

    // ---------------- phase A: H = relu(X @ W1 + b1), N=256 ----------------
    uint64_t acc[8][8];
#pragma unroll
    for (int i = 0; i < 8; i++)
#pragma unroll
        for (int m = 0; m < 8; m++) acc[i][m] = 0ull;

    stageA(0); CP_COMMIT();
    for (int c = 0; c < NCH; c++) {
        if (c + 1 < NCH) stageA(c + 1);
        CP_COMMIT();
        CP_WAIT1();
        __syncthreads();
        const float* Xb = (const float*)(smc + OFF_X + (c & 1) * 8704);
        const float* Wb = (const float*)(smc + OFF_W + (c & 1) * 34816);
#pragma unroll
        for (int kp = 0; kp < 16; kp++) {
            uint64_t xp[8];
#pragma unroll
            for (int i = 0; i < 8; i++)
                xp[i] = *(const uint64_t*)&Xb[(wid * 8 + i) * XS + kp * 2];
#pragma unroll
            for (int m = 0; m < 8; m++) {
                uint64_t wv = *(const uint64_t*)&Wb[(m * 32 + lane) * XS + kp * 2];
#pragma unroll
                for (int i = 0; i < 8; i++) ffma2(acc[i][m], xp[i], wv);
            }
        }
        __syncthreads();
    }

    // prefetch first W2 chunk, overlap with epilogue A
    stageB(0); CP_COMMIT();

    // epilogue A -> Hs
#pragma unroll
    for (int m = 0; m < 8; m++) {
        int col = m * 32 + lane;
        float b = B1[col];
#pragma unroll
        for (int i = 0; i < 8; i++)
            Hs[(wid * 8 + i) * HS + col] = fmaxf(sum2(acc[i][m]) + b, 0.f);
    }

    // ---------------- phase B: Y = relu(H @ W2 + b2), N=128 ----------------
    uint64_t acc2[8][4];
#pragma unroll
    for (int i = 0; i < 8; i++)
#pragma unroll
        for (int m = 0; m < 4; m++) acc2[i][m] = 0ull;

    for (int c = 0; c < 8; c++) {
        if (c + 1 < 8) stageB(c + 1);
        CP_COMMIT();
        CP_WAIT1();
        __syncthreads();
        const float* Wb = (const float*)(smc + OFF_W + (c & 1) * 34816);
#pragma unroll
        for (int kp = 0; kp < 16; kp++) {
            uint64_t xp[8];
#pragma unroll
            for (int i = 0; i < 8; i++)
                xp[i] = *(const uint64_t*)&Hs[(wid * 8 + i) * HS + c * 32 + kp * 2];
#pragma unroll
            for (int m = 0; m < 4; m++) {
                uint64_t wv = *(const uint64_t*)&Wb[(m * 32 + lane) * XS + kp * 2];
#pragma unroll
                for (int i = 0; i < 8; i++) ffma2(acc2[i][m], xp[i], wv);
            }
        }
        __syncthreads();
    }

    // ---------------- epilogue B: smem transpose -> vectorized global writes ----
    // Ys overlays the (now dead) Hs region with stride 132.
    {
        float* Ys = (float*)(smc + OFF_H);
#pragma unroll
        for (int i = 0; i < 8; i++) {
            int r = wid * 8 + i;
#pragma unroll
            for (int m = 0; m < 4; m++) {
                int col = m * 32 + lane;
                Ys[r * 132 + col] = fmaxf(sum2(acc2[i][m]) + B2[col], 0.f);
            }
        }
        __syncthreads();
        int r2 = tid >> 2, seg = tid & 3;
        int gr = row0 + r2;
        if (gr < rows) {
            int c0 = seg * 32;
            float4 v[8];
#pragma unroll
            for (int j = 0; j < 8; j++)
                v[j] = *(float4*)&Ys[r2 * 132 + c0 + j * 4];
            if (MODE == 1) {
                float* base = (TGT == 0 ? g_Sp : g_Sc) + (size_t)sB[r2] * D + c0;
#pragma unroll
                for (int j = 0; j < 8; j++) red4(base + j * 4, v[j]);
            } else if (MODE == 0) {
                float* dp = dst + (size_t)gr * D + c0;
#pragma unroll
                for (int j = 0; j < 8; j++) *(float4*)(dp + j * 4) = v[j];
            } else {
                float* dp = dst + (size_t)gr * D + c0;
#pragma unroll
                for (int j = 0; j < 8; j++) {
                    float4 o = *(float4*)(dp + j * 4);
                    v[j].x += o.x; v[j].y += o.y; v[j].z += o.z; v[j].w += o.w;
                    *(float4*)(dp + j * 4) = v[j];
                }
            }
        }
    }
}

// ---------------------------------------------------------------------------
extern "C" void kernel_launch(void* const* d_in, const int* in_sizes, int n_in,
                              void* d_out, int out_size) {
    const float* bt    = (const float*)d_in[0];
    const int*   si    = (const int*)  d_in[1];
    const int*   pi    = (const int*)  d_in[2];
    const float* rmask = (const float*)d_in[3];
    const float* lmask = (const float*)d_in[4];
    const float* stok  = (const float*)d_in[5];
    const float* etok  = (const float*)d_in[6];
    const float* Vw1 = (const float*)d_in[7],  *Vb1 = (const float*)d_in[8];
    const float* Vw2 = (const float*)d_in[9],  *Vb2 = (const float*)d_in[10];
    const float* Ew1 = (const float*)d_in[11], *Eb1 = (const float*)d_in[12];
    const float* Ew2 = (const float*)d_in[13], *Eb2 = (const float*)d_in[14];
    const float* Pw1 = (const float*)d_in[15], *Pb1 = (const float*)d_in[16];
    const float* Pw2 = (const float*)d_in[17], *Pb2 = (const float*)d_in[18];
    const float* Cw1 = (const float*)d_in[19], *Cb1 = (const float*)d_in[20];
    const float* Cw2 = (const float*)d_in[21], *Cb2 = (const float*)d_in[22];
    const float* Aw1 = (const float*)d_in[23], *Ab1 = (const float*)d_in[24];
    const float* Aw2 = (const float*)d_in[25], *Ab2 = (const float*)d_in[26];
    float* hid = (float*)d_out;

    cudaFuncSetAttribute(mlp9_k<128, 0, 0>, cudaFuncAttributeMaxDynamicSharedMemorySize, SMEMSZ);
    cudaFuncSetAttribute(mlp9_k<256, 1, 0>, cudaFuncAttributeMaxDynamicSharedMemorySize, SMEMSZ);
    cudaFuncSetAttribute(mlp9_k<256, 1, 1>, cudaFuncAttributeMaxDynamicSharedMemorySize, SMEMSZ);
    cudaFuncSetAttribute(mlp9_k<384, 2, 0>, cudaFuncAttributeMaxDynamicSharedMemorySize, SMEMSZ);

    const int gb = (NN + BR - 1) / BR;

    // ncu's effective skip landed on launch index 3 last round — put the V MLP there.
    prep_w1_k<<<128, 256>>>(Vw1, 128, 0);                 // 0
    prep_w2_k<<<128, 256>>>(Vw2, 0);                      // 1
    zero_cnt_k<<<(2 * NN + 255) / 256, 256>>>();          // 2
    mlp9_k<128, 0, 0><<<gb, NT, SMEMSZ>>>(NN, Vb1, Vb2, bt, nullptr, nullptr, hid);  // 3
    count_k<<<(EE + 255) / 256, 256>>>(si, pi);           // 4
    inv_k<<<(2 * NN + 255) / 256, 256>>>();               // 5
    edge_const_k<<<1, 256>>>(Ew1, Eb1, Ew2, Eb2);
    fold_bias_k<<<1, 256>>>(Pw1, Pb1, Cw1, Cb1);
    prep_w1_k<<<256, 256>>>(Pw1, 256, 1);
    prep_w1_k<<<256, 256>>>(Cw1, 256, 2);
    prep_w1_k<<<384, 256>>>(Aw1, 384, 3);
    prep_w2_k<<<128, 256>>>(Pw2, 1);
    prep_w2_k<<<128, 256>>>(Cw2, 2);
    prep_w2_k<<<128, 256>>>(Aw2, 3);

    for (int h = 0; h < 3; h++) {
        mlp9_k<256, 1, 0><<<gb, NT, SMEMSZ>>>(EE, nullptr, Pb2, hid, pi, si, nullptr);
        mlp9_k<256, 1, 1><<<gb, NT, SMEMSZ>>>(EE, nullptr, Cb2, hid, si, pi, nullptr);
        finalize_k<<<(NN * 32 + 255) / 256, 256>>>(rmask, lmask, stok, etok);
        mlp9_k<384, 2, 0><<<gb, NT, SMEMSZ>>>(NN, Ab1, Ab2, hid, nullptr, nullptr, hid);
    }
}